// round 3
// baseline (speedup 1.0000x reference)
#include <cuda_runtime.h>
#include <math.h>

// Problem dims
#define BB 128
#define RR 1152
#define CC 16
#define OO 16
#define COO 256          // C*O
#define II 8
#define RPB 8            // r per block in chunked kernels
#define NRC (RR / RPB)   // 144 r-chunks

// Scratch (static device globals; no dynamic allocation anywhere)
__device__ float g_uhat[RR * BB * COO];     // [r][b][co]  ~151 MB
__device__ float g_spart[NRC * BB * COO];   // per-chunk s partials ~18.9 MB
__device__ float g_zpart[NRC * CC];         // per-chunk Z partials
__device__ float g_b2[RR * CC];             // routing logits after iter 1
__device__ float g_v[BB * COO];             // current v  [b][c][o]

// ---------------------------------------------------------------------------
// K1: u_hat[r][b][co] = sum_i W[r][co][i] * x[b][r][i]
//     + fused partial sum over r (uniform c1 = 1/1152) into g_spart.
// grid: (4 b-groups, 144 r-chunks), 256 threads (thread t == co).
// ---------------------------------------------------------------------------
__global__ void __launch_bounds__(256) k_uhat(const float* __restrict__ x,
                                              const float* __restrict__ W) {
    int t  = threadIdx.x;           // co
    int bg = blockIdx.x;            // 0..3  -> b range [bg*32, bg*32+32)
    int rc = blockIdx.y;            // 0..143

    __shared__ float x_sm[32 * 8];

    float s_acc[32];
#pragma unroll
    for (int i = 0; i < 32; i++) s_acc[i] = 0.f;

    for (int rl = 0; rl < RPB; rl++) {
        int r = rc * RPB + rl;
        // W row for this co: 8 floats, 32B aligned
        float4 w0 = *(const float4*)&W[r * 2048 + t * 8];
        float4 w1 = *(const float4*)&W[r * 2048 + t * 8 + 4];
        // x tile: 32 b's x 8 i = 256 floats, one per thread
        {
            int bl = t >> 3, i = t & 7;
            x_sm[t] = x[((size_t)(bg * 32 + bl) * RR + r) * 8 + i];
        }
        __syncthreads();

        float* outp = &g_uhat[((size_t)r * BB + bg * 32) * COO + t];
#pragma unroll
        for (int bl = 0; bl < 32; bl++) {
            float4 xa = *(const float4*)&x_sm[bl * 8];
            float4 xb = *(const float4*)&x_sm[bl * 8 + 4];
            float u = w0.x * xa.x + w0.y * xa.y + w0.z * xa.z + w0.w * xa.w
                    + w1.x * xb.x + w1.y * xb.y + w1.z * xb.z + w1.w * xb.w;
            s_acc[bl] += u;
            outp[(size_t)bl * COO] = u;   // coalesced: 256 threads -> 1KB row
        }
        __syncthreads();
    }
#pragma unroll
    for (int bl = 0; bl < 32; bl++)
        g_spart[(size_t)rc * (BB * COO) + (bg * 32 + bl) * COO + t] = s_acc[bl];
}

// ---------------------------------------------------------------------------
// Reduce partials -> s, divide by Z (or by R for uniform iter-1 softmax),
// squash, write v (to g_v, or to d_out on the last iteration).
// grid: 128 blocks, 256 threads (one element each).
// ---------------------------------------------------------------------------
__global__ void __launch_bounds__(256) k_reduce(int use_z, float* __restrict__ dst) {
    __shared__ float z_sm[CC];
    int t = threadIdx.x;
    int idx = blockIdx.x * 256 + t;

    if (t < CC) {
        float z = 0.f;
        if (use_z) {
            for (int p = 0; p < NRC; p++) z += g_zpart[p * CC + t];
        } else {
            z = (float)RR;   // softmax(zeros) -> uniform 1/R
        }
        z_sm[t] = z;
    }
    __syncthreads();

    float s = 0.f;
#pragma unroll 8
    for (int p = 0; p < NRC; p++) s += g_spart[(size_t)p * (BB * COO) + idx];

    int c = (idx >> 4) & 15;
    s /= z_sm[c];
    // squash: v = s^2 * s / ((1+s^2) * sqrt(s^2))
    float sn = s * s;
    float v = sn * s / ((1.f + sn) * sqrtf(sn));
    if (dst) dst[idx] = v;
    else     g_v[idx] = v;
}

// ---------------------------------------------------------------------------
// Fused pass: for each r in the block's chunk
//   Phase A: a[r,c] = sum_{b,o} u_hat[b,r,c,o] * v[b,c,o]
//   then e[c] = exp(b_prev + a/128)  (local in r!), Z partial += e
//   Phase B: s_acc[b,co] += e[c] * u_hat   (smem accumulator, 128KB)
// first==1: b_prev = 0, stores b2 = a/128. first==0: b_prev = g_b2.
// Thread->element map: float4 index f = j*512 + t covers b = j*8 + (t>>6),
// co4 = (t&63). v is batch-dependent: preload vreg[j] = v[b(j)][co0..co0+3].
// grid: 144 blocks, 512 threads, dynamic smem ~132KB.
// ---------------------------------------------------------------------------
__global__ void __launch_bounds__(512, 1) k_pass(int first) {
    extern __shared__ float sm[];
    float*  s_acc = sm;                  // 32768 floats
    float*  a_sm  = sm + BB * COO;       // 16
    float*  e_sm  = a_sm + CC;           // 16
    float4* s_acc4 = (float4*)s_acc;

    int t   = threadIdx.x;               // 0..511
    int blk = blockIdx.x;                // 0..143

#pragma unroll
    for (int j = 0; j < 16; j++) s_acc4[j * 512 + t] = make_float4(0.f, 0.f, 0.f, 0.f);

    // Per-thread v values: for f = j*512 + t, b = j*8 + (t>>6), co0 = (t&63)*4
    int c   = (t & 63) >> 2;
    int co0 = (t & 63) * 4;
    int bp  = t >> 6;                    // 0..7
    float4 vreg[16];
#pragma unroll
    for (int j = 0; j < 16; j++)
        vreg[j] = *(const float4*)&g_v[(j * 8 + bp) * COO + co0];
    __syncthreads();

    float z_acc = 0.f;

    for (int rl = 0; rl < RPB; rl++) {
        int r = blk * RPB + rl;
        const float4* up = (const float4*)&g_uhat[(size_t)r * (BB * COO)];

        if (t < CC) a_sm[t] = 0.f;
        __syncthreads();

        // Phase A: a[r,c] = sum_{b,o} u_hat * v[b,c,o]
        float acc = 0.f;
#pragma unroll
        for (int j = 0; j < 16; j++) {
            float4 u = up[j * 512 + t];
            float4 vv = vreg[j];
            acc += u.x * vv.x + u.y * vv.y + u.z * vv.z + u.w * vv.w;
        }
        // reduce within 4-lane groups (same c), then one smem atomic per group
        acc += __shfl_xor_sync(0xffffffffu, acc, 1);
        acc += __shfl_xor_sync(0xffffffffu, acc, 2);
        if ((t & 3) == 0) atomicAdd(&a_sm[c], acc);
        __syncthreads();

        if (t < CC) {
            float bprev = first ? 0.f : g_b2[r * CC + t];
            float bn = bprev + a_sm[t] * (1.f / (float)BB);
            if (first) g_b2[r * CC + t] = bn;
            float e = expf(bn);
            e_sm[t] = e;
            z_acc += e;
        }
        __syncthreads();

        // Phase B: weighted accumulate into smem (re-read hits L1/L2)
        float e = e_sm[c];
#pragma unroll
        for (int j = 0; j < 16; j++) {
            float4 u  = up[j * 512 + t];
            float4 sv = s_acc4[j * 512 + t];
            sv.x += e * u.x; sv.y += e * u.y; sv.z += e * u.z; sv.w += e * u.w;
            s_acc4[j * 512 + t] = sv;
        }
        __syncthreads();
    }

    // write partials
#pragma unroll
    for (int j = 0; j < 16; j++)
        *(float4*)&g_spart[(size_t)blk * (BB * COO) + (j * 512 + t) * 4] =
            s_acc4[j * 512 + t];
    if (t < CC) g_zpart[blk * CC + t] = z_acc;
}

// ---------------------------------------------------------------------------
extern "C" void kernel_launch(void* const* d_in, const int* in_sizes, int n_in,
                              void* d_out, int out_size) {
    const float* x = (const float*)d_in[0];   // [128,1152,8]
    const float* W = (const float*)d_in[1];   // [1,1152,16,16,8]
    float* out = (float*)d_out;               // [128,16,16]

    const int smem_pass = (BB * COO + CC + CC) * (int)sizeof(float); // ~131KB
    cudaFuncSetAttribute(k_pass, cudaFuncAttributeMaxDynamicSharedMemorySize, smem_pass);

    dim3 g1(4, NRC);
    k_uhat<<<g1, 256>>>(x, W);                   // u_hat + s1 partials
    k_reduce<<<128, 256>>>(0, nullptr);          // v1 = squash(sum/1152)
    k_pass<<<NRC, 512, smem_pass>>>(1);          // a1 -> b2, s2num, Z2
    k_reduce<<<128, 256>>>(1, nullptr);          // v2 = squash(s2num/Z2)
    k_pass<<<NRC, 512, smem_pass>>>(0);          // a2, e=exp(b2+a2/128), s3num, Z3
    k_reduce<<<128, 256>>>(1, out);              // v3 -> d_out
}

// round 4
// speedup vs baseline: 1.1843x; 1.1843x over previous
#include <cuda_runtime.h>
#include <math.h>

#define BB 128
#define RR 1152
#define CC 16
#define OO 16
#define COO 256          // C*O
#define II 8
#define RPB 8            // r per block
#define NBLK (RR / RPB)  // 144

typedef unsigned long long ull;

// ---- packed f32x2 helpers (sm_103a FFMA2 path; PTX-only per SASS_PATTERNS) ----
__device__ __forceinline__ ull fma2(ull a, ull b, ull c) {
    ull d; asm("fma.rn.f32x2 %0, %1, %2, %3;" : "=l"(d) : "l"(a), "l"(b), "l"(c)); return d;
}
__device__ __forceinline__ ull pack2(float lo, float hi) {
    ull r; asm("mov.b64 %0, {%1, %2};" : "=l"(r) : "f"(lo), "f"(hi)); return r;
}
__device__ __forceinline__ void unpack2(ull p, float& lo, float& hi) {
    asm("mov.b64 {%0, %1}, %2;" : "=f"(lo), "=f"(hi) : "l"(p));
}

// ---- scratch (all L2-resident; no u_hat materialization anywhere) ----
__device__ float g_spart[NBLK * BB * COO];  // s partials [p][b][co]  ~18.9MB
__device__ float g_zpart[NBLK * CC];        // Z partials
__device__ float g_e[RR * CC];              // exp(b) routing weights
__device__ float g_b2[RR * CC];             // logits after iter 1
__device__ float g_v[BB * COO];             // current v [b][co]

__global__ void k_einit() {
    g_e[blockIdx.x * blockDim.x + threadIdx.x] = 1.f;   // grid covers RR*CC exactly
}

// ---------------------------------------------------------------------------
// k_s: s-partials[p][b][co] = sum_{r in chunk, i} x[b,r,i] * (e[r,c]*W[r,co,i])
// Dense 128x256x(8*8) micro-GEMM per r-chunk; thread tile 8b x 8co,
// co interleaved (co = cg + 32j) for conflict-free W loads; acc packed over
// b-pairs, x from smem broadcast LDS.128.
// grid: 144 blocks, 512 threads, smem ~97KB.
// ---------------------------------------------------------------------------
__global__ void __launch_bounds__(512, 1) k_s(const float* __restrict__ x,
                                              const float* __restrict__ W) {
    extern __shared__ float sm[];
    float* x_sm = sm;                  // [rl][i][b]   8*8*128 = 8192
    float* w_sm = sm + 8192;           // [rl][i][co]  8*8*256 = 16384 (e-premult)
    float* e_sm = sm + 8192 + 16384;   // [rl][c]      128

    int t  = threadIdx.x;
    int r0 = blockIdx.x * RPB;

    if (t < RPB * CC) e_sm[t] = g_e[(r0 + (t >> 4)) * CC + (t & 15)];
    __syncthreads();

    // x -> smem transposed [rl][i][b]
    for (int j = t; j < RPB * BB * II; j += 512) {
        int rl = j >> 10, rem = j & 1023, b = rem >> 3, i = rem & 7;
        x_sm[rl * 1024 + i * 128 + b] = x[((size_t)b * RR + r0 + rl) * II + i];
    }
    // W -> smem transposed [rl][i][co], multiplied by e[r,c]
    for (int q = t; q < RPB * 512; q += 512) {      // 512 float4 per r
        int rl = q >> 9, k = q & 511;
        int co = k >> 1, i0 = (k & 1) * 4;
        float4 wv = *(const float4*)&W[((size_t)(r0 + rl) * COO + co) * II + i0];
        float e = e_sm[rl * CC + (co >> 4)];
        float* wd = &w_sm[rl * 2048 + i0 * 256 + co];
        wd[0]   = wv.x * e;
        wd[256] = wv.y * e;
        wd[512] = wv.z * e;
        wd[768] = wv.w * e;
    }
    __syncthreads();

    int bg = t >> 5;        // b base = bg*8
    int cg = t & 31;        // co = cg + 32*j

    ull acc[4][8];
#pragma unroll
    for (int bp = 0; bp < 4; bp++)
#pragma unroll
        for (int j = 0; j < 8; j++) acc[bp][j] = 0ULL;

    for (int rl = 0; rl < RPB; rl++) {
#pragma unroll
        for (int i = 0; i < II; i++) {
            const ull* xp = (const ull*)&x_sm[rl * 1024 + i * 128 + bg * 8];
            ull x0 = xp[0], x1 = xp[1], x2 = xp[2], x3 = xp[3];
            const float* wr = &w_sm[rl * 2048 + i * 256 + cg];
#pragma unroll
            for (int j = 0; j < 8; j++) {
                float w = wr[32 * j];
                ull ww = pack2(w, w);
                acc[0][j] = fma2(x0, ww, acc[0][j]);
                acc[1][j] = fma2(x1, ww, acc[1][j]);
                acc[2][j] = fma2(x2, ww, acc[2][j]);
                acc[3][j] = fma2(x3, ww, acc[3][j]);
            }
        }
    }

    // write partials (coalesced scalar stores: lanes cover consecutive co)
    float* sp = &g_spart[(size_t)blockIdx.x * (BB * COO)];
#pragma unroll
    for (int bp = 0; bp < 4; bp++) {
        int b0 = bg * 8 + bp * 2;
#pragma unroll
        for (int j = 0; j < 8; j++) {
            float lo, hi; unpack2(acc[bp][j], lo, hi);
            sp[(size_t)b0 * COO + cg + 32 * j]       = lo;
            sp[(size_t)(b0 + 1) * COO + cg + 32 * j] = hi;
        }
    }
}

// ---------------------------------------------------------------------------
// k_a: per r: G[i][co] = sum_b x[b,r,i]*v[b,co]  (packed over i-pairs),
// then a[r,c] = (1/128) sum_{o,i} W[r,c,o,i]*G[i][c*16+o]  (shfl o-reduce),
// b_new = b_prev + a, e = exp(b_new), Z partials.
// grid: 144 blocks, 256 threads (t = co), smem 160KB (v + x chunk).
// ---------------------------------------------------------------------------
__global__ void __launch_bounds__(256, 1) k_a(const float* __restrict__ x,
                                              const float* __restrict__ W,
                                              int first) {
    extern __shared__ float sm[];
    float* v_sm = sm;            // [b][co] 32768
    float* x_sm = sm + 32768;    // [rl][b*8+i] 8192

    int t  = threadIdx.x;        // co
    int r0 = blockIdx.x * RPB;

    for (int j = t; j < 8192; j += 256)
        ((float4*)v_sm)[j] = ((const float4*)g_v)[j];
    for (int j = t; j < RPB * BB * II; j += 256) {
        int rl = j >> 10, rem = j & 1023;
        x_sm[rl * 1024 + rem] = x[((size_t)(rem >> 3) * RR + r0 + rl) * II + (rem & 7)];
    }
    __syncthreads();

    float z_acc = 0.f;
    for (int rl = 0; rl < RPB; rl++) {
        int r = r0 + rl;
        ull G2[4] = {0ULL, 0ULL, 0ULL, 0ULL};
        const float* xr = &x_sm[rl * 1024];
#pragma unroll 4
        for (int b = 0; b < BB; b++) {
            float vv = v_sm[b * COO + t];
            ull vv2 = pack2(vv, vv);
            const ull* xp = (const ull*)&xr[b * 8];
            G2[0] = fma2(xp[0], vv2, G2[0]);
            G2[1] = fma2(xp[1], vv2, G2[1]);
            G2[2] = fma2(xp[2], vv2, G2[2]);
            G2[3] = fma2(xp[3], vv2, G2[3]);
        }
        float G[8];
        unpack2(G2[0], G[0], G[1]); unpack2(G2[1], G[2], G[3]);
        unpack2(G2[2], G[4], G[5]); unpack2(G2[3], G[6], G[7]);

        const float4* wp = (const float4*)&W[((size_t)r * COO + t) * II];
        float4 w0 = wp[0], w1 = wp[1];
        float ap = w0.x * G[0] + w0.y * G[1] + w0.z * G[2] + w0.w * G[3]
                 + w1.x * G[4] + w1.y * G[5] + w1.z * G[6] + w1.w * G[7];
        ap += __shfl_xor_sync(0xffffffffu, ap, 1);
        ap += __shfl_xor_sync(0xffffffffu, ap, 2);
        ap += __shfl_xor_sync(0xffffffffu, ap, 4);
        ap += __shfl_xor_sync(0xffffffffu, ap, 8);
        if ((t & 15) == 0) {
            int c = t >> 4;
            float bprev = first ? 0.f : g_b2[r * CC + c];
            float bn = bprev + ap * (1.f / 128.f);
            if (first) g_b2[r * CC + c] = bn;
            float e = expf(bn);
            g_e[r * CC + c] = e;
            z_acc += e;
        }
    }
    if ((t & 15) == 0) g_zpart[blockIdx.x * CC + (t >> 4)] = z_acc;
}

// ---------------------------------------------------------------------------
// k_sred: s = sum_p spart / Z[c]; squash; write v (or final output).
// All reads are L2-resident now (no u_hat flood).
// ---------------------------------------------------------------------------
__global__ void __launch_bounds__(256) k_sred(int use_z, float* __restrict__ dst) {
    __shared__ float z_sm[CC];
    int t = threadIdx.x;
    int idx = blockIdx.x * 256 + t;

    if (t < CC) {
        float z = 0.f;
        if (use_z) {
            for (int p = 0; p < NBLK; p++) z += g_zpart[p * CC + t];
        } else {
            z = (float)RR;
        }
        z_sm[t] = z;
    }
    __syncthreads();

    float s = 0.f;
#pragma unroll 8
    for (int p = 0; p < NBLK; p++) s += g_spart[(size_t)p * (BB * COO) + idx];

    int c = (idx >> 4) & 15;
    s /= z_sm[c];
    float sn = s * s;
    float v = sn * s / ((1.f + sn) * sqrtf(sn));
    if (dst) dst[idx] = v;
    else     g_v[idx] = v;
}

// ---------------------------------------------------------------------------
extern "C" void kernel_launch(void* const* d_in, const int* in_sizes, int n_in,
                              void* d_out, int out_size) {
    const float* x = (const float*)d_in[0];   // [128,1152,8]
    const float* W = (const float*)d_in[1];   // [1,1152,16,16,8]
    float* out = (float*)d_out;               // [128,16,16]

    const int smem_s = (8192 + 16384 + 128) * (int)sizeof(float);  // ~97KB
    const int smem_a = (32768 + 8192) * (int)sizeof(float);        // 160KB
    cudaFuncSetAttribute(k_s, cudaFuncAttributeMaxDynamicSharedMemorySize, smem_s);
    cudaFuncSetAttribute(k_a, cudaFuncAttributeMaxDynamicSharedMemorySize, smem_a);

    k_einit<<<RR * CC / 256, 256>>>();            // e = 1 (uniform iter-1)
    k_s<<<NBLK, 512, smem_s>>>(x, W);             // s1 partials
    k_sred<<<128, 256>>>(0, nullptr);             // v1
    k_a<<<NBLK, 256, smem_a>>>(x, W, 1);          // a1 -> b2, e, Z
    k_s<<<NBLK, 512, smem_s>>>(x, W);             // s2 partials
    k_sred<<<128, 256>>>(1, nullptr);             // v2
    k_a<<<NBLK, 256, smem_a>>>(x, W, 0);          // a2 -> e, Z
    k_s<<<NBLK, 512, smem_s>>>(x, W);             // s3 partials
    k_sred<<<128, 256>>>(1, out);                 // v3 -> out
}

// round 5
// speedup vs baseline: 1.1851x; 1.0007x over previous
#include <cuda_runtime.h>
#include <math.h>

#define BB 128
#define RR 1152
#define CC 16
#define COO 256          // C*O
#define II 8
#define RPB 8            // r per block
#define NBLK (RR / RPB)  // 144

typedef unsigned long long ull;

// ---- packed f32x2 helpers (sm_103a FFMA2; PTX-only path) ----
__device__ __forceinline__ ull fma2(ull a, ull b, ull c) {
    ull d; asm("fma.rn.f32x2 %0, %1, %2, %3;" : "=l"(d) : "l"(a), "l"(b), "l"(c)); return d;
}
__device__ __forceinline__ ull pack2(float lo, float hi) {
    ull r; asm("mov.b64 %0, {%1, %2};" : "=l"(r) : "f"(lo), "f"(hi)); return r;
}
__device__ __forceinline__ void unpack2(ull p, float& lo, float& hi) {
    asm("mov.b64 {%0, %1}, %2;" : "=f"(lo), "=f"(hi) : "l"(p));
}

// ---- scratch (L2-resident) ----
__device__ float g_spart[NBLK * BB * COO];  // s partials [p][b][co] ~18.9MB
__device__ float g_zpart[NBLK * CC];        // Z partials
__device__ float g_b2[RR * CC];             // logits after iter 1
__device__ float g_v[BB * COO];             // current v [b][co]

// ---------------------------------------------------------------------------
// k_as: fused agreement + s-pass for one r-chunk of 8.
//  mode 0: skip agreement, e = 1 (iteration 1)
//  mode 1: a from v, bprev = 0, store b2, e = exp(b2)
//  mode 2: a from v, bprev = b2, e = exp(b2 + a)
// Phase A (512 thr = 2 b-halves x 256 co): G[i] = sum_b x[b,i]*v[b,co] packed
//   over i-pairs; a[r,c] via packed W-dot + shfl-o-reduce + smem atomics.
// Phase S: s_part[b][co] = sum_{rl,i} x[b,i] * (e[rl,c]*W[r,co,i]);
//   thread tile 8b x 8co, acc packed over co-pairs, x broadcast, W LDS.64.
// grid 144, 512 threads, smem ~224.6KB (1 CTA/SM, 16 warps).
// ---------------------------------------------------------------------------
__global__ void __launch_bounds__(512, 1) k_as(const float* __restrict__ x,
                                               const float* __restrict__ W,
                                               int mode) {
    extern __shared__ float sm[];
    float* v_sm = sm;              // [b][co]        32768
    float* x_sm = sm + 32768;      // [rl][b][i]      8192
    float* w_sm = sm + 40960;      // [rl][i][co]    16384 (e-premult)
    float* e_sm = sm + 57344;      // [rl][c]          128
    float* a_sm = sm + 57472;      // [c]               16

    int t  = threadIdx.x;
    int r0 = blockIdx.x * RPB;

    // stage x: [rl][b][i]
    for (int j = t; j < RPB * BB * II; j += 512) {
        int rl = j >> 10, rem = j & 1023;         // rem = b*8 + i
        x_sm[j] = x[((size_t)(rem >> 3) * RR + r0 + rl) * II + (rem & 7)];
    }
    if (mode) {
        for (int j = t; j < BB * COO / 4; j += 512)
            ((float4*)v_sm)[j] = ((const float4*)g_v)[j];
    }
    __syncthreads();

    // ---------------- Phase A ----------------
    if (mode) {
        int half = t >> 8;           // b-half
        int co   = t & 255;
        int c    = co >> 4;
        int b0   = half * 64;
        float z_acc = 0.f;

        for (int rl = 0; rl < RPB; rl++) {
            int r = r0 + rl;
            if (t < CC) a_sm[t] = 0.f;
            __syncthreads();

            ull G2[4] = {0ULL, 0ULL, 0ULL, 0ULL};
            const float* xr = &x_sm[rl * 1024];
#pragma unroll 4
            for (int bb = 0; bb < 64; bb++) {
                int b = b0 + bb;
                float vv = v_sm[b * COO + co];
                ull vv2 = pack2(vv, vv);
                const ull* xp = (const ull*)&xr[b * 8];
                G2[0] = fma2(xp[0], vv2, G2[0]);
                G2[1] = fma2(xp[1], vv2, G2[1]);
                G2[2] = fma2(xp[2], vv2, G2[2]);
                G2[3] = fma2(xp[3], vv2, G2[3]);
            }
            // packed W-dot: W i-pairs align with G2 i-pairs
            const ull* wp2 = (const ull*)&W[((size_t)r * COO + co) * II];
            ull ap2 = 0ULL;
            ap2 = fma2(wp2[0], G2[0], ap2);
            ap2 = fma2(wp2[1], G2[1], ap2);
            ap2 = fma2(wp2[2], G2[2], ap2);
            ap2 = fma2(wp2[3], G2[3], ap2);
            float alo, ahi; unpack2(ap2, alo, ahi);
            float ap = alo + ahi;
            ap += __shfl_xor_sync(0xffffffffu, ap, 1);
            ap += __shfl_xor_sync(0xffffffffu, ap, 2);
            ap += __shfl_xor_sync(0xffffffffu, ap, 4);
            ap += __shfl_xor_sync(0xffffffffu, ap, 8);
            if ((t & 15) == 0) atomicAdd(&a_sm[c], ap);
            __syncthreads();

            if (t < CC) {
                float bprev = (mode == 1) ? 0.f : g_b2[r * CC + t];
                float bn = bprev + a_sm[t] * (1.f / (float)BB);
                if (mode == 1) g_b2[r * CC + t] = bn;
                float e = expf(bn);
                e_sm[rl * CC + t] = e;
                z_acc += e;
            }
        }
        if (t < CC) g_zpart[blockIdx.x * CC + t] = z_acc;
        __syncthreads();
    } else {
        if (t < RPB * CC) e_sm[t] = 1.f;
        __syncthreads();
    }

    // ---------------- Phase S ----------------
    // stage W*e: [rl][i][co]
    for (int q = t; q < RPB * 512; q += 512) {
        int rl = q >> 9, k = q & 511;
        int co = k >> 1, i0 = (k & 1) * 4;
        float4 wv = *(const float4*)&W[((size_t)(r0 + rl) * COO + co) * II + i0];
        float e = e_sm[rl * CC + (co >> 4)];
        float* wd = &w_sm[rl * 2048 + i0 * 256 + co];
        wd[0]   = wv.x * e;
        wd[256] = wv.y * e;
        wd[512] = wv.z * e;
        wd[768] = wv.w * e;
    }
    __syncthreads();

    int bg = t >> 5;        // warp id: b base = bg*8 (uniform per warp)
    int cg = t & 31;        // co-pair p = cg + 32j  -> co = 2p

    ull acc[8][4];
#pragma unroll
    for (int bl = 0; bl < 8; bl++)
#pragma unroll
        for (int j = 0; j < 4; j++) acc[bl][j] = 0ULL;

    for (int rl = 0; rl < RPB; rl++) {
        const float* xr = &x_sm[rl * 1024 + bg * 64];   // x[rl][bg*8+bl][i]
        const float* wr = &w_sm[rl * 2048];
#pragma unroll
        for (int i = 0; i < II; i++) {
            const ull* wp = (const ull*)&wr[i * 256];
            ull w0 = wp[cg], w1 = wp[cg + 32], w2 = wp[cg + 64], w3 = wp[cg + 96];
#pragma unroll
            for (int bl = 0; bl < 8; bl++) {
                float xv = xr[bl * 8 + i];              // warp-broadcast
                ull x2 = pack2(xv, xv);
                acc[bl][0] = fma2(x2, w0, acc[bl][0]);
                acc[bl][1] = fma2(x2, w1, acc[bl][1]);
                acc[bl][2] = fma2(x2, w2, acc[bl][2]);
                acc[bl][3] = fma2(x2, w3, acc[bl][3]);
            }
        }
    }

    // store partials: pair at co = 2(cg+32j) -> coalesced 8B/lane
    float* sp = &g_spart[(size_t)blockIdx.x * (BB * COO)];
#pragma unroll
    for (int bl = 0; bl < 8; bl++) {
        int b = bg * 8 + bl;
#pragma unroll
        for (int j = 0; j < 4; j++)
            *(ull*)&sp[(size_t)b * COO + 2 * (cg + 32 * j)] = acc[bl][j];
    }
}

// ---------------------------------------------------------------------------
// k_sred: s = sum_p spart / Z[c]; squash; write v (or final output).
// grid 256 x 128 threads; spart is L2-hot.
// ---------------------------------------------------------------------------
__global__ void __launch_bounds__(128) k_sred(int use_z, float* __restrict__ dst) {
    __shared__ float z_sm[CC];
    int t = threadIdx.x;
    int idx = blockIdx.x * 128 + t;

    if (t < CC) {
        float z = 0.f;
        if (use_z) {
#pragma unroll 16
            for (int p = 0; p < NBLK; p++) z += g_zpart[p * CC + t];
        } else {
            z = (float)RR;
        }
        z_sm[t] = z;
    }
    __syncthreads();

    float s = 0.f;
#pragma unroll 16
    for (int p = 0; p < NBLK; p++) s += g_spart[(size_t)p * (BB * COO) + idx];

    int c = (idx >> 4) & 15;
    s /= z_sm[c];
    float sn = s * s;
    float v = sn * s / ((1.f + sn) * sqrtf(sn));
    if (dst) dst[idx] = v;
    else     g_v[idx] = v;
}

// ---------------------------------------------------------------------------
extern "C" void kernel_launch(void* const* d_in, const int* in_sizes, int n_in,
                              void* d_out, int out_size) {
    const float* x = (const float*)d_in[0];   // [128,1152,8]
    const float* W = (const float*)d_in[1];   // [1,1152,16,16,8]
    float* out = (float*)d_out;               // [128,16,16]

    const int smem_as = (32768 + 8192 + 16384 + 128 + 16) * (int)sizeof(float); // ~224.6KB
    cudaFuncSetAttribute(k_as, cudaFuncAttributeMaxDynamicSharedMemorySize, smem_as);

    k_as<<<NBLK, 512, smem_as>>>(x, W, 0);    // s1 partials (uniform e)
    k_sred<<<256, 128>>>(0, nullptr);         // v1
    k_as<<<NBLK, 512, smem_as>>>(x, W, 1);    // a1 -> b2, e2, s2 partials, Z2
    k_sred<<<256, 128>>>(1, nullptr);         // v2
    k_as<<<NBLK, 512, smem_as>>>(x, W, 2);    // a2 -> e3, s3 partials, Z3
    k_sred<<<256, 128>>>(1, out);             // v3 -> out
}

// round 7
// speedup vs baseline: 1.1888x; 1.0032x over previous
#include <cuda_runtime.h>
#include <math.h>

#define BB 128
#define RR 1152
#define CC 16
#define COO 256          // C*O
#define II 8
#define RPB 8            // r per block
#define NBLK (RR / RPB)  // 144

typedef unsigned long long ull;

// ---- packed f32x2 helpers (sm_103a FFMA2; PTX-only path) ----
__device__ __forceinline__ ull fma2(ull a, ull b, ull c) {
    ull d; asm("fma.rn.f32x2 %0, %1, %2, %3;" : "=l"(d) : "l"(a), "l"(b), "l"(c)); return d;
}
__device__ __forceinline__ ull pack2(float lo, float hi) {
    ull r; asm("mov.b64 %0, {%1, %2};" : "=l"(r) : "f"(lo), "f"(hi)); return r;
}
__device__ __forceinline__ void unpack2(ull p, float& lo, float& hi) {
    asm("mov.b64 {%0, %1}, %2;" : "=f"(lo), "=f"(hi) : "l"(p));
}

// ---- globals (L2-resident scratch; zero-init statics for the barrier) ----
__device__ float g_spart[NBLK * BB * COO];  // s partials [p][b][co] ~18.9MB
__device__ float g_zpart[NBLK * CC];        // Z partials
__device__ float g_v[BB * COO];             // current v [b][co]
__device__ unsigned g_count;                // barrier arrivals (returns to 0)
__device__ unsigned g_sense;                // monotonic across launches

// Software grid barrier (all NBLK CTAs co-resident: 144 blocks, 1 CTA/SM).
// Sense-reversal with monotonic sense: safe across graph replays because the
// sense only advances after ALL blocks arrive, and each block reads its base
// sense before its first arrival.
__device__ __forceinline__ void gridbar(unsigned& sense) {
    __threadfence();            // flush this thread's global writes
    __syncthreads();            // all block threads' writes fenced
    if (threadIdx.x == 0) {
        sense++;
        if (atomicAdd(&g_count, 1u) == NBLK - 1u) {
            g_count = 0;
            __threadfence();
            atomicExch(&g_sense, sense);
        } else {
            while (atomicAdd(&g_sense, 0u) != sense) __nanosleep(64);
        }
        __threadfence();
    }
    __syncthreads();
}

// ---------------------------------------------------------------------------
// Persistent kernel: 3 routing iterations, grid 144 x 512, smem ~225KB.
// Per iteration: [Phase A (it>0): a[r,c] -> e_sm]  [Phase S: spart]
//                gridbar  [reduce: s/Z -> squash -> v]  gridbar
// ---------------------------------------------------------------------------
__global__ void __launch_bounds__(512, 1) k_persist(const float* __restrict__ x,
                                                    const float* __restrict__ W,
                                                    float* __restrict__ out) {
    extern __shared__ float sm[];
    float* v_sm  = sm;              // [b][co]      32768
    float* x_sm  = sm + 32768;      // [rl][b][i]    8192
    float* w_sm  = sm + 40960;      // [rl][i][co]  16384 (e-premult)
    float* e_sm  = sm + 57344;      // [rl][c]        128
    float* a_sm  = sm + 57472;      // [c] (also Z)    16
    float* b2_sm = sm + 57488;      // [rl][c]        128

    int t   = threadIdx.x;
    int blk = blockIdx.x;
    int r0  = blk * RPB;

    unsigned sense = 0;
    if (t == 0) sense = atomicAdd(&g_sense, 0u);   // base sense for this launch

    // stage x once: [rl][b][i] (block's r-chunk fixed for all iterations)
    for (int j = t; j < RPB * BB * II; j += 512) {
        int rl = j >> 10, rem = j & 1023;          // rem = b*8 + i
        x_sm[j] = x[((size_t)(rem >> 3) * RR + r0 + rl) * II + (rem & 7)];
    }
    __syncthreads();

    for (int it = 0; it < 3; it++) {
        // ---------------- Phase A (agreement) ----------------
        if (it == 0) {
            if (t < RPB * CC) e_sm[t] = 1.f;       // uniform softmax(0)
            __syncthreads();
        } else {
            // stage v (bypass L1: written by other SMs last iteration)
            for (int j = t; j < BB * COO / 4; j += 512)
                ((float4*)v_sm)[j] = __ldcg(&((const float4*)g_v)[j]);
            __syncthreads();

            int half = t >> 8, co = t & 255, c = co >> 4, b0 = half * 64;
            float z_acc = 0.f;

            for (int rl = 0; rl < RPB; rl++) {
                int r = r0 + rl;
                if (t < CC) a_sm[t] = 0.f;
                __syncthreads();

                ull G2[4] = {0ULL, 0ULL, 0ULL, 0ULL};
                const float* xr = &x_sm[rl * 1024];
#pragma unroll 4
                for (int bb = 0; bb < 64; bb++) {
                    int b = b0 + bb;
                    float vv = v_sm[b * COO + co];
                    ull vv2 = pack2(vv, vv);
                    const ull* xp = (const ull*)&xr[b * 8];
                    G2[0] = fma2(xp[0], vv2, G2[0]);
                    G2[1] = fma2(xp[1], vv2, G2[1]);
                    G2[2] = fma2(xp[2], vv2, G2[2]);
                    G2[3] = fma2(xp[3], vv2, G2[3]);
                }
                const ull* wp2 = (const ull*)&W[((size_t)r * COO + co) * II];
                ull ap2 = 0ULL;
                ap2 = fma2(wp2[0], G2[0], ap2);
                ap2 = fma2(wp2[1], G2[1], ap2);
                ap2 = fma2(wp2[2], G2[2], ap2);
                ap2 = fma2(wp2[3], G2[3], ap2);
                float alo, ahi;
                unpack2(ap2, alo, ahi);
                float ap = alo + ahi;
                ap += __shfl_xor_sync(0xffffffffu, ap, 1);
                ap += __shfl_xor_sync(0xffffffffu, ap, 2);
                ap += __shfl_xor_sync(0xffffffffu, ap, 4);
                ap += __shfl_xor_sync(0xffffffffu, ap, 8);
                if ((t & 15) == 0) atomicAdd(&a_sm[c], ap);
                __syncthreads();

                if (t < CC) {
                    float bprev = (it == 1) ? 0.f : b2_sm[rl * CC + t];
                    float bn = bprev + a_sm[t] * (1.f / (float)BB);
                    if (it == 1) b2_sm[rl * CC + t] = bn;
                    float e = expf(bn);
                    e_sm[rl * CC + t] = e;
                    z_acc += e;
                }
            }
            if (t < CC) g_zpart[blk * CC + t] = z_acc;
            __syncthreads();
        }

        // ---------------- stage e-premultiplied W ----------------
        for (int q = t; q < RPB * 512; q += 512) {
            int rl = q >> 9, k = q & 511;
            int co = k >> 1, i0 = (k & 1) * 4;
            float4 wv = *(const float4*)&W[((size_t)(r0 + rl) * COO + co) * II + i0];
            float e = e_sm[rl * CC + (co >> 4)];
            float* wd = &w_sm[rl * 2048 + i0 * 256 + co];
            wd[0]   = wv.x * e;
            wd[256] = wv.y * e;
            wd[512] = wv.z * e;
            wd[768] = wv.w * e;
        }
        __syncthreads();

        // ---------------- Phase S ----------------
        {
            int bg = t >> 5;        // warp id: b base = bg*8
            int cg = t & 31;        // co-pair p = cg + 32j -> co = 2p

            ull acc[8][4];
#pragma unroll
            for (int bl = 0; bl < 8; bl++)
#pragma unroll
                for (int j = 0; j < 4; j++) acc[bl][j] = 0ULL;

            for (int rl = 0; rl < RPB; rl++) {
                const float* xr = &x_sm[rl * 1024 + bg * 64];
                const float* wr = &w_sm[rl * 2048];
#pragma unroll
                for (int i = 0; i < II; i++) {
                    const ull* wp = (const ull*)&wr[i * 256];
                    ull w0 = wp[cg], w1 = wp[cg + 32], w2 = wp[cg + 64], w3 = wp[cg + 96];
#pragma unroll
                    for (int bl = 0; bl < 8; bl++) {
                        float xv = xr[bl * 8 + i];
                        ull x2 = pack2(xv, xv);
                        acc[bl][0] = fma2(x2, w0, acc[bl][0]);
                        acc[bl][1] = fma2(x2, w1, acc[bl][1]);
                        acc[bl][2] = fma2(x2, w2, acc[bl][2]);
                        acc[bl][3] = fma2(x2, w3, acc[bl][3]);
                    }
                }
            }
            float* sp = &g_spart[(size_t)blk * (BB * COO)];
#pragma unroll
            for (int bl = 0; bl < 8; bl++) {
                int b = bg * 8 + bl;
#pragma unroll
                for (int j = 0; j < 4; j++)
                    *(ull*)&sp[(size_t)b * COO + 2 * (cg + 32 * j)] = acc[bl][j];
            }
        }

        gridbar(sense);

        // ---------------- reduce + squash ----------------
        if (t < CC) {
            float z;
            if (it == 0) {
                z = (float)RR;
            } else {
                z = 0.f;
#pragma unroll 8
                for (int p = 0; p < NBLK; p++) z += __ldcg(&g_zpart[p * CC + t]);
            }
            a_sm[t] = z;          // reuse a_sm as z_sm
        }
        __syncthreads();

        if (t < 228) {
            int idx = blk * 228 + t;
            if (idx < BB * COO) {
                float s = 0.f;
#pragma unroll 8
                for (int p = 0; p < NBLK; p++)
                    s += __ldcg(&g_spart[(size_t)p * (BB * COO) + idx]);
                int c = (idx >> 4) & 15;
                s /= a_sm[c];
                float sn = s * s;
                float v = sn * s / ((1.f + sn) * sqrtf(sn));
                if (it == 2) out[idx] = v;
                else         g_v[idx] = v;
            }
        }

        if (it < 2) gridbar(sense);
    }
}

// ---------------------------------------------------------------------------
extern "C" void kernel_launch(void* const* d_in, const int* in_sizes, int n_in,
                              void* d_out, int out_size) {
    const float* x = (const float*)d_in[0];   // [128,1152,8]
    const float* W = (const float*)d_in[1];   // [1,1152,16,16,8]
    float* out = (float*)d_out;               // [128,16,16]

    const int smem = (32768 + 8192 + 16384 + 128 + 16 + 128) * (int)sizeof(float); // ~225KB
    cudaFuncSetAttribute(k_persist, cudaFuncAttributeMaxDynamicSharedMemorySize, smem);
    k_persist<<<NBLK, 512, smem>>>(x, W, out);
}

// round 11
// speedup vs baseline: 1.2022x; 1.0112x over previous
#include <cuda_runtime.h>
#include <math.h>

#define BB 128
#define RR 1152
#define CC 16
#define COO 256          // C*O
#define II 8
#define RPB 8            // r per block
#define NBLK (RR / RPB)  // 144

typedef unsigned long long ull;

// ---- packed f32x2 helpers (sm_103a FFMA2; PTX-only path) ----
__device__ __forceinline__ ull fma2(ull a, ull b, ull c) {
    ull d; asm("fma.rn.f32x2 %0, %1, %2, %3;" : "=l"(d) : "l"(a), "l"(b), "l"(c)); return d;
}
__device__ __forceinline__ ull pack2(float lo, float hi) {
    ull r; asm("mov.b64 %0, {%1, %2};" : "=l"(r) : "f"(lo), "f"(hi)); return r;
}
__device__ __forceinline__ void unpack2(ull p, float& lo, float& hi) {
    asm("mov.b64 {%0, %1}, %2;" : "=f"(lo), "=f"(hi) : "l"(p));
}

// ---- globals ----
__device__ float g_spart[NBLK * BB * COO];  // s partials [p][b][co] ~18.9MB
__device__ float g_zpart[NBLK * CC];        // Z partials
__device__ float g_v[BB * COO];             // current v [b][co]
__device__ unsigned g_count;                // barrier arrivals (returns to 0)
__device__ unsigned g_sense;                // monotonic across launches

// Software grid barrier (144 CTAs, 1/SM, all co-resident).
__device__ __forceinline__ void gridbar(unsigned& sense) {
    __threadfence();
    __syncthreads();
    if (threadIdx.x == 0) {
        sense++;
        if (atomicAdd(&g_count, 1u) == NBLK - 1u) {
            g_count = 0;
            __threadfence();
            atomicExch(&g_sense, sense);
        } else {
            while (atomicAdd(&g_sense, 0u) != sense) __nanosleep(64);
        }
        __threadfence();
    }
    __syncthreads();
}

// ---------------------------------------------------------------------------
// Persistent kernel: 3 routing iterations, grid 144 x 1024, smem ~225KB.
// ---------------------------------------------------------------------------
__global__ void __launch_bounds__(1024, 1) k_persist(const float* __restrict__ x,
                                                     const float* __restrict__ W,
                                                     float* __restrict__ out) {
    extern __shared__ float sm[];
    float* v_sm  = sm;              // [b][co]      32768
    float* x_sm  = sm + 32768;      // [rl][b][i]    8192
    float* w_sm  = sm + 40960;      // [rl][i][co]  16384 (e-premult; reused as red scratch)
    float* e_sm  = sm + 57344;      // [rl][c]        128
    float* a_sm  = sm + 57472;      // [c] (also Z)    16
    float* b2_sm = sm + 57488;      // [rl][c]        128

    int t   = threadIdx.x;
    int blk = blockIdx.x;
    int r0  = blk * RPB;

    unsigned sense = 0;
    if (t == 0) sense = atomicAdd(&g_sense, 0u);

    // stage x once: [rl][b][i]
    for (int j = t; j < RPB * BB * II; j += 1024) {
        int rl = j >> 10, rem = j & 1023;          // rem = b*8 + i
        x_sm[j] = x[((size_t)(rem >> 3) * RR + r0 + rl) * II + (rem & 7)];
    }
    __syncthreads();

    for (int it = 0; it < 3; it++) {
        // ---------------- Phase A (agreement) ----------------
        if (it == 0) {
            if (t < RPB * CC) e_sm[t] = 1.f;
            __syncthreads();
        } else {
            for (int j = t; j < BB * COO / 4; j += 1024)
                ((float4*)v_sm)[j] = __ldcg(&((const float4*)g_v)[j]);
            __syncthreads();

            int q  = t >> 8;            // b-quarter 0..3
            int co = t & 255;
            int c  = co >> 4;
            int b0 = q * 32;
            float z_acc = 0.f;

            for (int rl = 0; rl < RPB; rl++) {
                int r = r0 + rl;
                if (t < CC) a_sm[t] = 0.f;
                __syncthreads();

                ull G2[4] = {0ULL, 0ULL, 0ULL, 0ULL};
                const float* xr = &x_sm[rl * 1024];
#pragma unroll 8
                for (int bb = 0; bb < 32; bb++) {
                    int b = b0 + bb;
                    float vv = v_sm[b * COO + co];
                    ull vv2 = pack2(vv, vv);
                    const ull* xp = (const ull*)&xr[b * 8];   // warp-broadcast LDS.64
                    G2[0] = fma2(xp[0], vv2, G2[0]);
                    G2[1] = fma2(xp[1], vv2, G2[1]);
                    G2[2] = fma2(xp[2], vv2, G2[2]);
                    G2[3] = fma2(xp[3], vv2, G2[3]);
                }
                const ull* wp2 = (const ull*)&W[((size_t)r * COO + co) * II];
                ull ap2 = 0ULL;
                ap2 = fma2(wp2[0], G2[0], ap2);
                ap2 = fma2(wp2[1], G2[1], ap2);
                ap2 = fma2(wp2[2], G2[2], ap2);
                ap2 = fma2(wp2[3], G2[3], ap2);
                float alo, ahi;
                unpack2(ap2, alo, ahi);
                float ap = alo + ahi;
                ap += __shfl_xor_sync(0xffffffffu, ap, 1);
                ap += __shfl_xor_sync(0xffffffffu, ap, 2);
                ap += __shfl_xor_sync(0xffffffffu, ap, 4);
                ap += __shfl_xor_sync(0xffffffffu, ap, 8);
                if ((t & 15) == 0) atomicAdd(&a_sm[c], ap);
                __syncthreads();

                if (t < CC) {
                    float bprev = (it == 1) ? 0.f : b2_sm[rl * CC + t];
                    float bn = bprev + a_sm[t] * (1.f / (float)BB);
                    if (it == 1) b2_sm[rl * CC + t] = bn;
                    float e = expf(bn);
                    e_sm[rl * CC + t] = e;
                    z_acc += e;
                }
            }
            if (t < CC) g_zpart[blk * CC + t] = z_acc;
            __syncthreads();
        }

        // ---------------- stage e-premultiplied W ----------------
        for (int qq = t; qq < RPB * 512; qq += 1024) {
            int rl = qq >> 9, k = qq & 511;
            int co = k >> 1, i0 = (k & 1) * 4;
            float4 wv = *(const float4*)&W[((size_t)(r0 + rl) * COO + co) * II + i0];
            float e = e_sm[rl * CC + (co >> 4)];
            float* wd = &w_sm[rl * 2048 + i0 * 256 + co];
            wd[0]   = wv.x * e;
            wd[256] = wv.y * e;
            wd[512] = wv.z * e;
            wd[768] = wv.w * e;
        }
        __syncthreads();

        // ---------------- Phase S ----------------
        {
            int wid  = t >> 5;      // 0..31: b base = wid*4
            int lane = t & 31;      // copair p = lane + 32j -> co = 2p

            ull acc[4][4];
#pragma unroll
            for (int bl = 0; bl < 4; bl++)
#pragma unroll
                for (int j = 0; j < 4; j++) acc[bl][j] = 0ULL;

            for (int rl = 0; rl < RPB; rl++) {
                const float* xr = &x_sm[rl * 1024 + wid * 32];   // x[rl][wid*4+bl][i]
                const float* wr = &w_sm[rl * 2048];
#pragma unroll
                for (int i = 0; i < II; i++) {
                    const ull* wp = (const ull*)&wr[i * 256];
                    ull w0 = wp[lane], w1 = wp[lane + 32], w2 = wp[lane + 64], w3 = wp[lane + 96];
#pragma unroll
                    for (int bl = 0; bl < 4; bl++) {
                        float xv = xr[bl * 8 + i];               // warp-broadcast
                        ull x2 = pack2(xv, xv);
                        acc[bl][0] = fma2(x2, w0, acc[bl][0]);
                        acc[bl][1] = fma2(x2, w1, acc[bl][1]);
                        acc[bl][2] = fma2(x2, w2, acc[bl][2]);
                        acc[bl][3] = fma2(x2, w3, acc[bl][3]);
                    }
                }
            }
            float* sp = &g_spart[(size_t)blk * (BB * COO)];
#pragma unroll
            for (int bl = 0; bl < 4; bl++) {
                int b = wid * 4 + bl;
#pragma unroll
                for (int j = 0; j < 4; j++)
                    *(ull*)&sp[(size_t)b * COO + 2 * (lane + 32 * j)] = acc[bl][j];
            }
        }

        gridbar(sense);

        // ---------------- reduce + squash ----------------
        if (t < CC) {
            float z;
            if (it == 0) {
                z = (float)RR;
            } else {
                z = 0.f;
#pragma unroll 8
                for (int p = 0; p < NBLK; p++) z += __ldcg(&g_zpart[p * CC + t]);
            }
            a_sm[t] = z;
        }
        // 4-way split partial sum into w_sm scratch (w_sm free until next iter)
        {
            int g = t >> 8, tt = t & 255;
            float s = 0.f;
            if (tt < 228) {
                int idx = blk * 228 + tt;
                if (idx < BB * COO) {
                    int p0 = g * 36;
#pragma unroll 9
                    for (int p = p0; p < p0 + 36; p++)
                        s += __ldcg(&g_spart[(size_t)p * (BB * COO) + idx]);
                }
            }
            w_sm[g * 256 + tt] = s;
        }
        __syncthreads();

        if (t < 228) {
            int idx = blk * 228 + t;
            if (idx < BB * COO) {
                float s = w_sm[t] + w_sm[256 + t] + w_sm[512 + t] + w_sm[768 + t];
                int c = (idx >> 4) & 15;
                s /= a_sm[c];
                float sn = s * s;
                float v = sn * s / ((1.f + sn) * sqrtf(sn));
                if (it == 2) out[idx] = v;
                else         g_v[idx] = v;
            }
        }

        if (it < 2) gridbar(sense);
        else __syncthreads();
    }
}

// ---------------------------------------------------------------------------
extern "C" void kernel_launch(void* const* d_in, const int* in_sizes, int n_in,
                              void* d_out, int out_size) {
    const float* x = (const float*)d_in[0];   // [128,1152,8]
    const float* W = (const float*)d_in[1];   // [1,1152,16,16,8]
    float* out = (float*)d_out;               // [128,16,16]

    const int smem = (32768 + 8192 + 16384 + 128 + 16 + 128) * (int)sizeof(float); // ~225KB
    cudaFuncSetAttribute(k_persist, cudaFuncAttributeMaxDynamicSharedMemorySize, smem);
    k_persist<<<NBLK, 1024, smem>>>(x, W, out);
}